// round 10
// baseline (speedup 1.0000x reference)
#include <cuda_runtime.h>
#include <cuda_bf16.h>
#include <stdint.h>
#include <math.h>

#define BATCH 8
#define SEQ   1024
#define DEMB  1024
#define NHEAD 16
#define DHEAD 64
#define MROWS (BATCH*SEQ)   // 8192

// ------------------------- scratch (device globals) -------------------------
__device__ __align__(16) __nv_bfloat16 g_Qhi[(size_t)BATCH*NHEAD*SEQ*DHEAD];
__device__ __align__(16) __nv_bfloat16 g_Qlo[(size_t)BATCH*NHEAD*SEQ*DHEAD];
__device__ __align__(16) __nv_bfloat16 g_Khi[(size_t)BATCH*NHEAD*SEQ*DHEAD];
__device__ __align__(16) __nv_bfloat16 g_Klo[(size_t)BATCH*NHEAD*SEQ*DHEAD];
__device__ __align__(16) __nv_bfloat16 g_Vthi[(size_t)BATCH*NHEAD*DHEAD*SEQ];  // [B,H,64,N]
__device__ __align__(16) __nv_bfloat16 g_Vtlo[(size_t)BATCH*NHEAD*DHEAD*SEQ];

__device__ __align__(16) __nv_bfloat16 g_Xhi[(size_t)MROWS*DEMB];
__device__ __align__(16) __nv_bfloat16 g_Xlo[(size_t)MROWS*DEMB];
__device__ __align__(16) __nv_bfloat16 g_WqThi[(size_t)3072*1024];
__device__ __align__(16) __nv_bfloat16 g_WqTlo[(size_t)3072*1024];
__device__ __align__(16) __nv_bfloat16 g_WpThi[(size_t)1024*1024];
__device__ __align__(16) __nv_bfloat16 g_WpTlo[(size_t)1024*1024];
__device__ __align__(16) __nv_bfloat16 g_Ohi[(size_t)MROWS*DEMB];
__device__ __align__(16) __nv_bfloat16 g_Olo[(size_t)MROWS*DEMB];

// ------------------------- helpers -------------------------
__device__ __forceinline__ uint32_t smem_u32(const void* p) {
    uint32_t a;
    asm("{ .reg .u64 t; cvta.to.shared.u64 t, %1; cvt.u32.u64 %0, t; }" : "=r"(a) : "l"(p));
    return a;
}
__device__ __forceinline__ void mma_bf16(float* d, const uint32_t* a, const uint32_t* b) {
    asm volatile("mma.sync.aligned.m16n8k16.row.col.f32.bf16.bf16.f32 "
                 "{%0,%1,%2,%3}, {%4,%5,%6,%7}, {%8,%9}, {%0,%1,%2,%3};"
                 : "+f"(d[0]), "+f"(d[1]), "+f"(d[2]), "+f"(d[3])
                 : "r"(a[0]), "r"(a[1]), "r"(a[2]), "r"(a[3]), "r"(b[0]), "r"(b[1]));
}
__device__ __forceinline__ void cp16(uint32_t dst, const void* src) {
    asm volatile("cp.async.cg.shared.global [%0], [%1], 16;" :: "r"(dst), "l"(src));
}
__device__ __forceinline__ void split2(float v, __nv_bfloat16& h, __nv_bfloat16& l) {
    h = __float2bfloat16(v);
    l = __float2bfloat16(v - __bfloat162float(h));
}
__device__ __forceinline__ void pack_split(float x, float y, uint32_t& hi, uint32_t& lo) {
    __nv_bfloat16 xh, xl, yh, yl;
    split2(x, xh, xl); split2(y, yh, yl);
    __nv_bfloat162 h2(xh, yh), l2(xl, yl);
    hi = *(uint32_t*)&h2; lo = *(uint32_t*)&l2;
}
// FMA-pipe exp; valid for x <= 0; rel err ~2e-6.
__device__ __forceinline__ float fast_exp(float x) {
    float y = fmaxf(x * 1.44269504088896340736f, -120.0f);
    float t = y + 12582912.0f;
    float n = t - 12582912.0f;
    float f = y - n;
    float p =        1.3333558e-3f;
    p = fmaf(p, f,   9.6181291e-3f);
    p = fmaf(p, f,   5.5504109e-2f);
    p = fmaf(p, f,   2.4022651e-1f);
    p = fmaf(p, f,   6.9314718e-1f);
    p = fmaf(p, f,   1.0f);
    int e = (int)n;
    float s = __int_as_float((e + 127) << 23);
    return p * s;
}

// ------------------------- conversion kernels -------------------------
__global__ __launch_bounds__(256) void cvt_x_kernel(const float4* __restrict__ X)
{
    __nv_bfloat162* hi = (__nv_bfloat162*)g_Xhi;
    __nv_bfloat162* lo = (__nv_bfloat162*)g_Xlo;
    int i = blockIdx.x * 256 + threadIdx.x;
    float4 v = X[i];
    __nv_bfloat16 h0,l0,h1,l1,h2,l2,h3,l3;
    split2(v.x,h0,l0); split2(v.y,h1,l1); split2(v.z,h2,l2); split2(v.w,h3,l3);
    hi[2*i]   = __nv_bfloat162(h0,h1); hi[2*i+1] = __nv_bfloat162(h2,h3);
    lo[2*i]   = __nv_bfloat162(l0,l1); lo[2*i+1] = __nv_bfloat162(l2,l3);
}

template<int WSEL>
__global__ __launch_bounds__(256) void cvt_wT_kernel(const float* __restrict__ W)
{
    const int ncols = (WSEL == 0) ? 3072 : 1024;
    __nv_bfloat16* hiT = (WSEL == 0) ? g_WqThi : g_WpThi;
    __nv_bfloat16* loT = (WSEL == 0) ? g_WqTlo : g_WpTlo;

    __shared__ float t[32][33];
    const int n0 = blockIdx.x * 32, k0 = blockIdx.y * 32;
    const int tx = threadIdx.x, ty = threadIdx.y;
    #pragma unroll
    for (int r = ty; r < 32; r += 8)
        t[r][tx] = W[(size_t)(k0 + r) * ncols + n0 + tx];
    __syncthreads();
    #pragma unroll
    for (int rr = ty; rr < 32; rr += 8) {
        float v = t[tx][rr];
        __nv_bfloat16 h, l; split2(v, h, l);
        size_t o = (size_t)(n0 + rr) * 1024 + k0 + tx;
        hiT[o] = h; loT[o] = l;
    }
}

// ------------------------- mma.sync split-bf16 GEMM, cp.async 3-stage --------
#define KC     64
#define SKC    72
#define HALFE  (128*SKC)          // elems per matrix per stage
#define STG_E  (2*HALFE)          // elems per stage (A+B)
#define NCH    48
#define NSTG   3
#define GDYN   (NSTG*STG_E*2)     // 110592 bytes

template<int MODE>   // 0: qkv (scatter hi/lo Q,K,Vt), 1: proj (store fp32)
__global__ __launch_bounds__(256, 1) void gemm_bf16_kernel(
    const float* __restrict__ bias, float* __restrict__ out)
{
    const __nv_bfloat16* __restrict__ Ahi = (MODE == 0) ? g_Xhi   : g_Ohi;
    const __nv_bfloat16* __restrict__ Alo = (MODE == 0) ? g_Xlo   : g_Olo;
    const __nv_bfloat16* __restrict__ Bhi = (MODE == 0) ? g_WqThi : g_WpThi;
    const __nv_bfloat16* __restrict__ Blo = (MODE == 0) ? g_WqTlo : g_WpTlo;

    extern __shared__ __align__(16) __nv_bfloat16 smem_dyn[];
    const uint32_t sb = smem_u32(smem_dyn);

    const int tid  = threadIdx.x;
    const int wid  = tid >> 5, lane = tid & 31;
    const int wm   = wid & 3;
    const int wn   = wid >> 2;
    const int bn   = blockIdx.x * 128;
    const int bm   = blockIdx.y * 128;

    float acc[2][8][4];
    #pragma unroll
    for (int mt = 0; mt < 2; mt++)
        #pragma unroll
        for (int n = 0; n < 8; n++)
            #pragma unroll
            for (int c = 0; c < 4; c++) acc[mt][n][c] = 0.f;

    // issue chunk i's loads into stage i%3 (8 x cp.async.16B per thread) + commit
    auto issue = [&](int i) {
        const int p  = i >> 4;                  // 0: hi*hi, 1: hi*lo, 2: lo*hi
        const int k0 = (i & 15) * KC;
        const __nv_bfloat16* Ap = (p == 2) ? Alo : Ahi;
        const __nv_bfloat16* Bp = (p == 1) ? Blo : Bhi;
        const uint32_t st = sb + (uint32_t)(i % NSTG) * (STG_E * 2);
        #pragma unroll
        for (int q = 0; q < 4; q++) {
            int idx = q * 256 + tid;
            int row = idx >> 3;
            int col = (idx & 7) * 8;
            uint32_t so = (uint32_t)(row * SKC + col) * 2;
            cp16(st + so,             Ap + (size_t)(bm + row) * 1024 + k0 + col);
            cp16(st + HALFE * 2 + so, Bp + (size_t)(bn + row) * 1024 + k0 + col);
        }
        asm volatile("cp.async.commit_group;" ::: "memory");
    };

    issue(0);
    issue(1);

    for (int i = 0; i < NCH; i++) {
        asm volatile("cp.async.wait_group 1;" ::: "memory");   // chunk i landed
        __syncthreads();                                       // WAR: stage (i-1)%3 free

        if (i + 2 < NCH) issue(i + 2);                         // into stage (i+2)%3=(i-1)%3
        else asm volatile("cp.async.commit_group;" ::: "memory");  // keep group count aligned

        const __nv_bfloat16* sA = smem_dyn + (i % NSTG) * STG_E;
        const __nv_bfloat16* sB = sA + HALFE;

        #pragma unroll
        for (int ks = 0; ks < 4; ks++) {
            const int kb = ks * 16 + (lane & 3) * 2;
            uint32_t afr[2][4];
            #pragma unroll
            for (int mt = 0; mt < 2; mt++) {
                int r0 = wm * 32 + mt * 16 + (lane >> 2);
                afr[mt][0] = *(const uint32_t*)(sA + (size_t)r0 * SKC + kb);
                afr[mt][1] = *(const uint32_t*)(sA + (size_t)(r0 + 8) * SKC + kb);
                afr[mt][2] = *(const uint32_t*)(sA + (size_t)r0 * SKC + kb + 8);
                afr[mt][3] = *(const uint32_t*)(sA + (size_t)(r0 + 8) * SKC + kb + 8);
            }
            uint32_t bfr[8][2];
            #pragma unroll
            for (int n = 0; n < 8; n++) {
                int nr = wn * 64 + n * 8 + (lane >> 2);
                bfr[n][0] = *(const uint32_t*)(sB + (size_t)nr * SKC + kb);
                bfr[n][1] = *(const uint32_t*)(sB + (size_t)nr * SKC + kb + 8);
            }
            #pragma unroll
            for (int mt = 0; mt < 2; mt++)
                #pragma unroll
                for (int n = 0; n < 8; n++)
                    mma_bf16(acc[mt][n], afr[mt], bfr[n]);
        }
    }

    // ---- epilogue ----
    #pragma unroll
    for (int mt = 0; mt < 2; mt++) {
        #pragma unroll
        for (int half = 0; half < 2; half++) {
            int gr = bm + wm * 32 + mt * 16 + (lane >> 2) + half * 8;
            if (MODE == 0) {
                const int bb = gr >> 10, nn = gr & 1023;
                #pragma unroll
                for (int n = 0; n < 8; n++) {
                    #pragma unroll
                    for (int e = 0; e < 2; e++) {
                        int gc = bn + wn * 64 + n * 8 + 2 * (lane & 3) + e;
                        float v = acc[mt][n][half * 2 + e] + bias[gc];
                        int h  = gc / 192;
                        int rr = gc - h * 192;
                        int dd = rr / 3;
                        int which = rr - dd * 3;
                        __nv_bfloat16 vh, vl; split2(v, vh, vl);
                        if (which == 2) {
                            size_t idx = ((size_t)(bb * NHEAD + h) * DHEAD + dd) * SEQ + nn;
                            g_Vthi[idx] = vh; g_Vtlo[idx] = vl;
                        } else {
                            size_t idx = ((size_t)(bb * NHEAD + h) * SEQ + nn) * DHEAD + dd;
                            if (which == 0) { g_Qhi[idx] = vh; g_Qlo[idx] = vl; }
                            else            { g_Khi[idx] = vh; g_Klo[idx] = vl; }
                        }
                    }
                }
            } else {
                #pragma unroll
                for (int n = 0; n < 8; n++) {
                    int gc = bn + wn * 64 + n * 8 + 2 * (lane & 3);
                    float2 v = make_float2(acc[mt][n][half*2]   + bias[gc],
                                           acc[mt][n][half*2+1] + bias[gc + 1]);
                    *(float2*)(out + (size_t)gr * 1024 + gc) = v;
                }
            }
        }
    }
}

// ------------------------- tensor-core flash attention (unchanged) ----------
#define FSKC 72
#define FMAT (64*FSKC)
#define FBUF (4*FMAT)
#define FDYN (FBUF*2*2)

__global__ __launch_bounds__(256, 1) void flash_tc_kernel()
{
    extern __shared__ __align__(16) __nv_bfloat16 fsm[];
    const int tid  = threadIdx.x;
    const int wid  = tid >> 5, lane = tid & 31;
    const int bh   = blockIdx.x;
    const int qr   = blockIdx.y * 128 + wid * 16 + (lane >> 2);
    const int qc   = (lane & 3) * 2;

    uint32_t qh[4][4], ql[4][4];
    {
        const __nv_bfloat16* Qh = g_Qhi + ((size_t)bh * SEQ + qr) * DHEAD;
        const __nv_bfloat16* Ql = g_Qlo + ((size_t)bh * SEQ + qr) * DHEAD;
        #pragma unroll
        for (int kk = 0; kk < 4; kk++) {
            int c = kk * 16 + qc;
            qh[kk][0] = *(const uint32_t*)(Qh + c);
            qh[kk][1] = *(const uint32_t*)(Qh + 8 * DHEAD + c);
            qh[kk][2] = *(const uint32_t*)(Qh + c + 8);
            qh[kk][3] = *(const uint32_t*)(Qh + 8 * DHEAD + c + 8);
            ql[kk][0] = *(const uint32_t*)(Ql + c);
            ql[kk][1] = *(const uint32_t*)(Ql + 8 * DHEAD + c);
            ql[kk][2] = *(const uint32_t*)(Ql + c + 8);
            ql[kk][3] = *(const uint32_t*)(Ql + 8 * DHEAD + c + 8);
        }
    }

    float o[8][4];
    #pragma unroll
    for (int n = 0; n < 8; n++)
        #pragma unroll
        for (int c = 0; c < 4; c++) o[n][c] = 0.f;
    float m0 = 0.f, m1 = 0.f, l0 = 0.f, l1 = 0.f;

    uint4 pre[8];
    auto issue_load = [&](int t) {
        const int key0 = t * 64;
        #pragma unroll
        for (int i = 0; i < 2; i++) {
            int u = i * 256 + tid;
            int row = u >> 3, c8 = (u & 7) * 8;
            size_t koff = ((size_t)bh * SEQ + key0 + row) * DHEAD + c8;
            size_t voff = ((size_t)bh * DHEAD + row) * SEQ + key0 + c8;
            pre[i]     = *(const uint4*)(g_Khi  + koff);
            pre[2 + i] = *(const uint4*)(g_Klo  + koff);
            pre[4 + i] = *(const uint4*)(g_Vthi + voff);
            pre[6 + i] = *(const uint4*)(g_Vtlo + voff);
        }
    };
    issue_load(0);

    for (int t = 0; t < SEQ / 64; t++) {
        __nv_bfloat16* buf = fsm + (t & 1) * FBUF;
        __nv_bfloat16* sKh = buf;
        __nv_bfloat16* sKl = buf + FMAT;
        __nv_bfloat16* sVh = buf + 2 * FMAT;
        __nv_bfloat16* sVl = buf + 3 * FMAT;

        #pragma unroll
        for (int i = 0; i < 2; i++) {
            int u = i * 256 + tid;
            int row = u >> 3, c8 = (u & 7) * 8;
            *(uint4*)(sKh + row * FSKC + c8) = pre[i];
            *(uint4*)(sKl + row * FSKC + c8) = pre[2 + i];
            *(uint4*)(sVh + row * FSKC + c8) = pre[4 + i];
            *(uint4*)(sVl + row * FSKC + c8) = pre[6 + i];
        }
        if (t + 1 < SEQ / 64) issue_load(t + 1);
        __syncthreads();

        float S[8][4];
        #pragma unroll
        for (int n = 0; n < 8; n++)
            #pragma unroll
            for (int c = 0; c < 4; c++) S[n][c] = 0.f;

        #pragma unroll
        for (int kk = 0; kk < 4; kk++) {
            const int kb = kk * 16 + qc;
            uint32_t kf[8][2];
            #pragma unroll
            for (int n = 0; n < 8; n++) {
                int nr = n * 8 + (lane >> 2);
                kf[n][0] = *(const uint32_t*)(sKh + nr * FSKC + kb);
                kf[n][1] = *(const uint32_t*)(sKh + nr * FSKC + kb + 8);
            }
            #pragma unroll
            for (int n = 0; n < 8; n++) {
                mma_bf16(S[n], qh[kk], kf[n]);
                mma_bf16(S[n], ql[kk], kf[n]);
            }
            #pragma unroll
            for (int n = 0; n < 8; n++) {
                int nr = n * 8 + (lane >> 2);
                kf[n][0] = *(const uint32_t*)(sKl + nr * FSKC + kb);
                kf[n][1] = *(const uint32_t*)(sKl + nr * FSKC + kb + 8);
            }
            #pragma unroll
            for (int n = 0; n < 8; n++)
                mma_bf16(S[n], qh[kk], kf[n]);
        }

        float tm0 = S[0][0], tm1 = S[0][2];
        #pragma unroll
        for (int n = 0; n < 8; n++) {
            tm0 = fmaxf(tm0, fmaxf(S[n][0], S[n][1]));
            tm1 = fmaxf(tm1, fmaxf(S[n][2], S[n][3]));
        }
        tm0 = fmaxf(tm0, __shfl_xor_sync(0xffffffffu, tm0, 1));
        tm0 = fmaxf(tm0, __shfl_xor_sync(0xffffffffu, tm0, 2));
        tm1 = fmaxf(tm1, __shfl_xor_sync(0xffffffffu, tm1, 1));
        tm1 = fmaxf(tm1, __shfl_xor_sync(0xffffffffu, tm1, 2));
        float nm0 = fmaxf(m0, tm0), nm1 = fmaxf(m1, tm1);
        float a0 = fast_exp(m0 - nm0), a1 = fast_exp(m1 - nm1);
        m0 = nm0; m1 = nm1;
        float ps0 = 0.f, ps1 = 0.f;
        #pragma unroll
        for (int n = 0; n < 8; n++) {
            S[n][0] = fast_exp(S[n][0] - nm0); ps0 += S[n][0];
            S[n][1] = fast_exp(S[n][1] - nm0); ps0 += S[n][1];
            S[n][2] = fast_exp(S[n][2] - nm1); ps1 += S[n][2];
            S[n][3] = fast_exp(S[n][3] - nm1); ps1 += S[n][3];
        }
        ps0 += __shfl_xor_sync(0xffffffffu, ps0, 1);
        ps0 += __shfl_xor_sync(0xffffffffu, ps0, 2);
        ps1 += __shfl_xor_sync(0xffffffffu, ps1, 1);
        ps1 += __shfl_xor_sync(0xffffffffu, ps1, 2);
        l0 = l0 * a0 + ps0;
        l1 = l1 * a1 + ps1;
        #pragma unroll
        for (int n = 0; n < 8; n++) {
            o[n][0] *= a0; o[n][1] *= a0;
            o[n][2] *= a1; o[n][3] *= a1;
        }

        #pragma unroll
        for (int kk = 0; kk < 4; kk++) {
            uint32_t ph[4], pl[4];
            pack_split(S[2*kk][0],   S[2*kk][1],   ph[0], pl[0]);
            pack_split(S[2*kk][2],   S[2*kk][3],   ph[1], pl[1]);
            pack_split(S[2*kk+1][0], S[2*kk+1][1], ph[2], pl[2]);
            pack_split(S[2*kk+1][2], S[2*kk+1][3], ph[3], pl[3]);

            const int kb = kk * 16 + qc;
            uint32_t vf[8][2];
            #pragma unroll
            for (int n = 0; n < 8; n++) {
                int nr = n * 8 + (lane >> 2);
                vf[n][0] = *(const uint32_t*)(sVh + nr * FSKC + kb);
                vf[n][1] = *(const uint32_t*)(sVh + nr * FSKC + kb + 8);
            }
            #pragma unroll
            for (int n = 0; n < 8; n++) {
                mma_bf16(o[n], ph, vf[n]);
                mma_bf16(o[n], pl, vf[n]);
            }
            #pragma unroll
            for (int n = 0; n < 8; n++) {
                int nr = n * 8 + (lane >> 2);
                vf[n][0] = *(const uint32_t*)(sVl + nr * FSKC + kb);
                vf[n][1] = *(const uint32_t*)(sVl + nr * FSKC + kb + 8);
            }
            #pragma unroll
            for (int n = 0; n < 8; n++)
                mma_bf16(o[n], ph, vf[n]);
        }
    }

    const float inv0 = 1.0f / (l0 * 32.0f);
    const float inv1 = 1.0f / (l1 * 32.0f);
    const int bb = bh >> 4, hh = bh & 15;
    size_t base0 = ((size_t)(bb * SEQ + qr)) * DEMB + hh * DHEAD;
    size_t base1 = base0 + (size_t)8 * DEMB;
    #pragma unroll
    for (int n = 0; n < 8; n++) {
        int col = n * 8 + qc;
        uint32_t h0, l0w, h1, l1w;
        pack_split(o[n][0] * inv0, o[n][1] * inv0, h0, l0w);
        pack_split(o[n][2] * inv1, o[n][3] * inv1, h1, l1w);
        *(uint32_t*)(g_Ohi + base0 + col) = h0;
        *(uint32_t*)(g_Olo + base0 + col) = l0w;
        *(uint32_t*)(g_Ohi + base1 + col) = h1;
        *(uint32_t*)(g_Olo + base1 + col) = l1w;
    }
}

// ---------------------------------------------------------------------------
extern "C" void kernel_launch(void* const* d_in, const int* in_sizes, int n_in,
                              void* d_out, int out_size)
{
    const float* x      = (const float*)d_in[0];
    const float* w_qkv  = (const float*)d_in[1];
    const float* b_qkv  = (const float*)d_in[2];
    const float* w_proj = (const float*)d_in[3];
    const float* b_proj = (const float*)d_in[4];
    float* out = (float*)d_out;

    static int attr_set = 0;
    if (!attr_set) {
        cudaFuncSetAttribute(gemm_bf16_kernel<0>, cudaFuncAttributeMaxDynamicSharedMemorySize, GDYN);
        cudaFuncSetAttribute(gemm_bf16_kernel<1>, cudaFuncAttributeMaxDynamicSharedMemorySize, GDYN);
        cudaFuncSetAttribute(flash_tc_kernel,     cudaFuncAttributeMaxDynamicSharedMemorySize, FDYN);
        attr_set = 1;
    }

    cvt_x_kernel<<<8192, 256>>>((const float4*)x);
    cvt_wT_kernel<0><<<dim3(96, 32), dim3(32, 8)>>>(w_qkv);
    cvt_wT_kernel<1><<<dim3(32, 32), dim3(32, 8)>>>(w_proj);

    gemm_bf16_kernel<0><<<dim3(3072/128, MROWS/128), 256, GDYN>>>(b_qkv, nullptr);

    flash_tc_kernel<<<dim3(BATCH*NHEAD, SEQ/128), 256, FDYN>>>();

    gemm_bf16_kernel<1><<<dim3(1024/128, MROWS/128), 256, GDYN>>>(b_proj, out);
}

// round 11
// speedup vs baseline: 1.0352x; 1.0352x over previous
#include <cuda_runtime.h>
#include <cuda_bf16.h>
#include <stdint.h>
#include <math.h>

#define BATCH 8
#define SEQ   1024
#define DEMB  1024
#define NHEAD 16
#define DHEAD 64
#define MROWS (BATCH*SEQ)   // 8192

// ------------------------- scratch (device globals) -------------------------
__device__ __align__(16) __nv_bfloat16 g_Qhi[(size_t)BATCH*NHEAD*SEQ*DHEAD];
__device__ __align__(16) __nv_bfloat16 g_Qlo[(size_t)BATCH*NHEAD*SEQ*DHEAD];
__device__ __align__(16) __nv_bfloat16 g_Khi[(size_t)BATCH*NHEAD*SEQ*DHEAD];
__device__ __align__(16) __nv_bfloat16 g_Klo[(size_t)BATCH*NHEAD*SEQ*DHEAD];
__device__ __align__(16) __nv_bfloat16 g_Vthi[(size_t)BATCH*NHEAD*DHEAD*SEQ];  // [B,H,64,N]
__device__ __align__(16) __nv_bfloat16 g_Vtlo[(size_t)BATCH*NHEAD*DHEAD*SEQ];

__device__ __align__(16) __nv_bfloat16 g_Xhi[(size_t)MROWS*DEMB];
__device__ __align__(16) __nv_bfloat16 g_Xlo[(size_t)MROWS*DEMB];
__device__ __align__(16) __nv_bfloat16 g_WqThi[(size_t)3072*1024];
__device__ __align__(16) __nv_bfloat16 g_WqTlo[(size_t)3072*1024];
__device__ __align__(16) __nv_bfloat16 g_WpThi[(size_t)1024*1024];
__device__ __align__(16) __nv_bfloat16 g_WpTlo[(size_t)1024*1024];
__device__ __align__(16) __nv_bfloat16 g_Ohi[(size_t)MROWS*DEMB];
__device__ __align__(16) __nv_bfloat16 g_Olo[(size_t)MROWS*DEMB];

// ------------------------- helpers -------------------------
__device__ __forceinline__ uint32_t smem_u32(const void* p) {
    uint32_t a;
    asm("{ .reg .u64 t; cvta.to.shared.u64 t, %1; cvt.u32.u64 %0, t; }" : "=r"(a) : "l"(p));
    return a;
}
__device__ __forceinline__ void mma_bf16(float* d, const uint32_t* a, const uint32_t* b) {
    asm volatile("mma.sync.aligned.m16n8k16.row.col.f32.bf16.bf16.f32 "
                 "{%0,%1,%2,%3}, {%4,%5,%6,%7}, {%8,%9}, {%0,%1,%2,%3};"
                 : "+f"(d[0]), "+f"(d[1]), "+f"(d[2]), "+f"(d[3])
                 : "r"(a[0]), "r"(a[1]), "r"(a[2]), "r"(a[3]), "r"(b[0]), "r"(b[1]));
}
__device__ __forceinline__ void ldm_x4(uint32_t addr, uint32_t& r0, uint32_t& r1,
                                       uint32_t& r2, uint32_t& r3) {
    asm volatile("ldmatrix.sync.aligned.m8n8.x4.shared.b16 {%0,%1,%2,%3}, [%4];"
                 : "=r"(r0), "=r"(r1), "=r"(r2), "=r"(r3) : "r"(addr));
}
__device__ __forceinline__ void split2(float v, __nv_bfloat16& h, __nv_bfloat16& l) {
    h = __float2bfloat16(v);
    l = __float2bfloat16(v - __bfloat162float(h));
}
__device__ __forceinline__ void pack_split(float x, float y, uint32_t& hi, uint32_t& lo) {
    __nv_bfloat16 xh, xl, yh, yl;
    split2(x, xh, xl); split2(y, yh, yl);
    __nv_bfloat162 h2(xh, yh), l2(xl, yl);
    hi = *(uint32_t*)&h2; lo = *(uint32_t*)&l2;
}
// FMA-pipe exp; valid for x <= 0; rel err ~2e-6.
__device__ __forceinline__ float fast_exp(float x) {
    float y = fmaxf(x * 1.44269504088896340736f, -120.0f);
    float t = y + 12582912.0f;
    float n = t - 12582912.0f;
    float f = y - n;
    float p =        1.3333558e-3f;
    p = fmaf(p, f,   9.6181291e-3f);
    p = fmaf(p, f,   5.5504109e-2f);
    p = fmaf(p, f,   2.4022651e-1f);
    p = fmaf(p, f,   6.9314718e-1f);
    p = fmaf(p, f,   1.0f);
    int e = (int)n;
    float s = __int_as_float((e + 127) << 23);
    return p * s;
}

// ------------------------- conversion kernels -------------------------
__global__ __launch_bounds__(256) void cvt_x_kernel(const float4* __restrict__ X)
{
    __nv_bfloat162* hi = (__nv_bfloat162*)g_Xhi;
    __nv_bfloat162* lo = (__nv_bfloat162*)g_Xlo;
    int i = blockIdx.x * 256 + threadIdx.x;
    float4 v = X[i];
    __nv_bfloat16 h0,l0,h1,l1,h2,l2,h3,l3;
    split2(v.x,h0,l0); split2(v.y,h1,l1); split2(v.z,h2,l2); split2(v.w,h3,l3);
    hi[2*i]   = __nv_bfloat162(h0,h1); hi[2*i+1] = __nv_bfloat162(h2,h3);
    lo[2*i]   = __nv_bfloat162(l0,l1); lo[2*i+1] = __nv_bfloat162(l2,l3);
}

template<int WSEL>
__global__ __launch_bounds__(256) void cvt_wT_kernel(const float* __restrict__ W)
{
    const int ncols = (WSEL == 0) ? 3072 : 1024;
    __nv_bfloat16* hiT = (WSEL == 0) ? g_WqThi : g_WpThi;
    __nv_bfloat16* loT = (WSEL == 0) ? g_WqTlo : g_WpTlo;

    __shared__ float t[32][33];
    const int n0 = blockIdx.x * 32, k0 = blockIdx.y * 32;
    const int tx = threadIdx.x, ty = threadIdx.y;
    #pragma unroll
    for (int r = ty; r < 32; r += 8)
        t[r][tx] = W[(size_t)(k0 + r) * ncols + n0 + tx];
    __syncthreads();
    #pragma unroll
    for (int rr = ty; rr < 32; rr += 8) {
        float v = t[tx][rr];
        __nv_bfloat16 h, l; split2(v, h, l);
        size_t o = (size_t)(n0 + rr) * 1024 + k0 + tx;
        hiT[o] = h; loT[o] = l;
    }
}

// ------------------------- mma.sync split-bf16 GEMM (ldmatrix mainloop) -----
// Double-buffered smem + register prefetch (proven R9 scheme); fragment loads
// via ldmatrix.x4 (24 LDSM/chunk/warp instead of 96 LDS.32).
#define KC    64
#define SKC   72
#define HALFE (128*SKC)           // elems per matrix per buffer
#define NCH   48
#define GDYN  (4*HALFE*2)         // 73728 bytes

template<int MODE>   // 0: qkv (scatter hi/lo Q,K,Vt), 1: proj (store fp32)
__global__ __launch_bounds__(256, 1) void gemm_bf16_kernel(
    const float* __restrict__ bias, float* __restrict__ out)
{
    const __nv_bfloat16* __restrict__ Ahi = (MODE == 0) ? g_Xhi   : g_Ohi;
    const __nv_bfloat16* __restrict__ Alo = (MODE == 0) ? g_Xlo   : g_Olo;
    const __nv_bfloat16* __restrict__ Bhi = (MODE == 0) ? g_WqThi : g_WpThi;
    const __nv_bfloat16* __restrict__ Blo = (MODE == 0) ? g_WqTlo : g_WpTlo;

    extern __shared__ __align__(16) __nv_bfloat16 smem_dyn[];
    const uint32_t sb = smem_u32(smem_dyn);

    const int tid  = threadIdx.x;
    const int wid  = tid >> 5, lane = tid & 31;
    const int wm   = wid & 3;
    const int wn   = wid >> 2;
    const int bn   = blockIdx.x * 128;
    const int bm   = blockIdx.y * 128;

    float acc[2][8][4];
    #pragma unroll
    for (int mt = 0; mt < 2; mt++)
        #pragma unroll
        for (int n = 0; n < 8; n++)
            #pragma unroll
            for (int c = 0; c < 4; c++) acc[mt][n][c] = 0.f;

    // precomputed ldmatrix lane address offsets (within a matrix, bytes)
    const int lm_a_row = (lane & 15);                 // A: 16 rows, 2 col-halves
    const int lm_a_ch  = (lane >> 4) << 3;
    const int lm_b_row = (lane & 7) + (((lane >> 3) & 1) << 3);   // B: 16 rows
    const int lm_b_ch  = (lane >> 4) << 3;

    uint4 ra[4], rb[4];
    auto issue_loads = [&](int i) {
        const int p  = i >> 4;                  // 0: hi*hi, 1: hi*lo, 2: lo*hi
        const int k0 = (i & 15) * KC;
        const __nv_bfloat16* Ap = (p == 2) ? Alo : Ahi;
        const __nv_bfloat16* Bp = (p == 1) ? Blo : Bhi;
        #pragma unroll
        for (int q = 0; q < 4; q++) {
            int idx = q * 256 + tid;
            int row = idx >> 3;
            int col = (idx & 7) * 8;
            ra[q] = *(const uint4*)(Ap + (size_t)(bm + row) * 1024 + k0 + col);
            rb[q] = *(const uint4*)(Bp + (size_t)(bn + row) * 1024 + k0 + col);
        }
    };
    issue_loads(0);

    for (int i = 0; i < NCH; i++) {
        const int bsel = i & 1;
        __nv_bfloat16* sA = smem_dyn + bsel * 2 * HALFE;
        __nv_bfloat16* sB = sA + HALFE;
        const uint32_t aAddr = sb + (uint32_t)bsel * (4 * HALFE);   // bytes
        const uint32_t bAddr = aAddr + 2 * HALFE;

        #pragma unroll
        for (int q = 0; q < 4; q++) {
            int idx = q * 256 + tid;
            int row = idx >> 3;
            int col = (idx & 7) * 8;
            *(uint4*)(sA + row * SKC + col) = ra[q];
            *(uint4*)(sB + row * SKC + col) = rb[q];
        }
        if (i + 1 < NCH) issue_loads(i + 1);
        __syncthreads();

        #pragma unroll
        for (int ks = 0; ks < 4; ks++) {
            const int cb = ks * 16;
            // A fragments via ldmatrix.x4: rows (wm*32+mt*16+lane&15), col half
            uint32_t afr[2][4];
            #pragma unroll
            for (int mt = 0; mt < 2; mt++) {
                int row = wm * 32 + mt * 16 + lm_a_row;
                int col = cb + lm_a_ch;
                ldm_x4(aAddr + (uint32_t)(row * SKC + col) * 2,
                       afr[mt][0], afr[mt][1], afr[mt][2], afr[mt][3]);
            }
            // B fragments: 4 x ldmatrix.x4 covering 8 n-tiles x 2 k-halves
            uint32_t bfr[8][2];
            #pragma unroll
            for (int ng = 0; ng < 4; ng++) {
                int row = wn * 64 + ng * 16 + lm_b_row;
                int col = cb + lm_b_ch;
                uint32_t r0, r1, r2, r3;
                ldm_x4(bAddr + (uint32_t)(row * SKC + col) * 2, r0, r1, r2, r3);
                bfr[2*ng][0]   = r0; bfr[2*ng][1]   = r2;
                bfr[2*ng+1][0] = r1; bfr[2*ng+1][1] = r3;
            }
            #pragma unroll
            for (int mt = 0; mt < 2; mt++)
                #pragma unroll
                for (int n = 0; n < 8; n++)
                    mma_bf16(acc[mt][n], afr[mt], bfr[n]);
        }
    }

    // ---- epilogue ----
    #pragma unroll
    for (int mt = 0; mt < 2; mt++) {
        #pragma unroll
        for (int half = 0; half < 2; half++) {
            int gr = bm + wm * 32 + mt * 16 + (lane >> 2) + half * 8;
            if (MODE == 0) {
                const int bb = gr >> 10, nn = gr & 1023;
                #pragma unroll
                for (int n = 0; n < 8; n++) {
                    #pragma unroll
                    for (int e = 0; e < 2; e++) {
                        int gc = bn + wn * 64 + n * 8 + 2 * (lane & 3) + e;
                        float v = acc[mt][n][half * 2 + e] + bias[gc];
                        int h  = gc / 192;
                        int rr = gc - h * 192;
                        int dd = rr / 3;
                        int which = rr - dd * 3;
                        __nv_bfloat16 vh, vl; split2(v, vh, vl);
                        if (which == 2) {
                            size_t idx = ((size_t)(bb * NHEAD + h) * DHEAD + dd) * SEQ + nn;
                            g_Vthi[idx] = vh; g_Vtlo[idx] = vl;
                        } else {
                            size_t idx = ((size_t)(bb * NHEAD + h) * SEQ + nn) * DHEAD + dd;
                            if (which == 0) { g_Qhi[idx] = vh; g_Qlo[idx] = vl; }
                            else            { g_Khi[idx] = vh; g_Klo[idx] = vl; }
                        }
                    }
                }
            } else {
                #pragma unroll
                for (int n = 0; n < 8; n++) {
                    int gc = bn + wn * 64 + n * 8 + 2 * (lane & 3);
                    float2 v = make_float2(acc[mt][n][half*2]   + bias[gc],
                                           acc[mt][n][half*2+1] + bias[gc + 1]);
                    *(float2*)(out + (size_t)gr * 1024 + gc) = v;
                }
            }
        }
    }
}

// ------------------------- tensor-core flash attention (unchanged) ----------
#define FSKC 72
#define FMAT (64*FSKC)
#define FBUF (4*FMAT)
#define FDYN (FBUF*2*2)

__global__ __launch_bounds__(256, 1) void flash_tc_kernel()
{
    extern __shared__ __align__(16) __nv_bfloat16 fsm[];
    const int tid  = threadIdx.x;
    const int wid  = tid >> 5, lane = tid & 31;
    const int bh   = blockIdx.x;
    const int qr   = blockIdx.y * 128 + wid * 16 + (lane >> 2);
    const int qc   = (lane & 3) * 2;

    uint32_t qh[4][4], ql[4][4];
    {
        const __nv_bfloat16* Qh = g_Qhi + ((size_t)bh * SEQ + qr) * DHEAD;
        const __nv_bfloat16* Ql = g_Qlo + ((size_t)bh * SEQ + qr) * DHEAD;
        #pragma unroll
        for (int kk = 0; kk < 4; kk++) {
            int c = kk * 16 + qc;
            qh[kk][0] = *(const uint32_t*)(Qh + c);
            qh[kk][1] = *(const uint32_t*)(Qh + 8 * DHEAD + c);
            qh[kk][2] = *(const uint32_t*)(Qh + c + 8);
            qh[kk][3] = *(const uint32_t*)(Qh + 8 * DHEAD + c + 8);
            ql[kk][0] = *(const uint32_t*)(Ql + c);
            ql[kk][1] = *(const uint32_t*)(Ql + 8 * DHEAD + c);
            ql[kk][2] = *(const uint32_t*)(Ql + c + 8);
            ql[kk][3] = *(const uint32_t*)(Ql + 8 * DHEAD + c + 8);
        }
    }

    float o[8][4];
    #pragma unroll
    for (int n = 0; n < 8; n++)
        #pragma unroll
        for (int c = 0; c < 4; c++) o[n][c] = 0.f;
    float m0 = 0.f, m1 = 0.f, l0 = 0.f, l1 = 0.f;

    uint4 pre[8];
    auto issue_load = [&](int t) {
        const int key0 = t * 64;
        #pragma unroll
        for (int i = 0; i < 2; i++) {
            int u = i * 256 + tid;
            int row = u >> 3, c8 = (u & 7) * 8;
            size_t koff = ((size_t)bh * SEQ + key0 + row) * DHEAD + c8;
            size_t voff = ((size_t)bh * DHEAD + row) * SEQ + key0 + c8;
            pre[i]     = *(const uint4*)(g_Khi  + koff);
            pre[2 + i] = *(const uint4*)(g_Klo  + koff);
            pre[4 + i] = *(const uint4*)(g_Vthi + voff);
            pre[6 + i] = *(const uint4*)(g_Vtlo + voff);
        }
    };
    issue_load(0);

    for (int t = 0; t < SEQ / 64; t++) {
        __nv_bfloat16* buf = fsm + (t & 1) * FBUF;
        __nv_bfloat16* sKh = buf;
        __nv_bfloat16* sKl = buf + FMAT;
        __nv_bfloat16* sVh = buf + 2 * FMAT;
        __nv_bfloat16* sVl = buf + 3 * FMAT;

        #pragma unroll
        for (int i = 0; i < 2; i++) {
            int u = i * 256 + tid;
            int row = u >> 3, c8 = (u & 7) * 8;
            *(uint4*)(sKh + row * FSKC + c8) = pre[i];
            *(uint4*)(sKl + row * FSKC + c8) = pre[2 + i];
            *(uint4*)(sVh + row * FSKC + c8) = pre[4 + i];
            *(uint4*)(sVl + row * FSKC + c8) = pre[6 + i];
        }
        if (t + 1 < SEQ / 64) issue_load(t + 1);
        __syncthreads();

        float S[8][4];
        #pragma unroll
        for (int n = 0; n < 8; n++)
            #pragma unroll
            for (int c = 0; c < 4; c++) S[n][c] = 0.f;

        #pragma unroll
        for (int kk = 0; kk < 4; kk++) {
            const int kb = kk * 16 + qc;
            uint32_t kf[8][2];
            #pragma unroll
            for (int n = 0; n < 8; n++) {
                int nr = n * 8 + (lane >> 2);
                kf[n][0] = *(const uint32_t*)(sKh + nr * FSKC + kb);
                kf[n][1] = *(const uint32_t*)(sKh + nr * FSKC + kb + 8);
            }
            #pragma unroll
            for (int n = 0; n < 8; n++) {
                mma_bf16(S[n], qh[kk], kf[n]);
                mma_bf16(S[n], ql[kk], kf[n]);
            }
            #pragma unroll
            for (int n = 0; n < 8; n++) {
                int nr = n * 8 + (lane >> 2);
                kf[n][0] = *(const uint32_t*)(sKl + nr * FSKC + kb);
                kf[n][1] = *(const uint32_t*)(sKl + nr * FSKC + kb + 8);
            }
            #pragma unroll
            for (int n = 0; n < 8; n++)
                mma_bf16(S[n], qh[kk], kf[n]);
        }

        float tm0 = S[0][0], tm1 = S[0][2];
        #pragma unroll
        for (int n = 0; n < 8; n++) {
            tm0 = fmaxf(tm0, fmaxf(S[n][0], S[n][1]));
            tm1 = fmaxf(tm1, fmaxf(S[n][2], S[n][3]));
        }
        tm0 = fmaxf(tm0, __shfl_xor_sync(0xffffffffu, tm0, 1));
        tm0 = fmaxf(tm0, __shfl_xor_sync(0xffffffffu, tm0, 2));
        tm1 = fmaxf(tm1, __shfl_xor_sync(0xffffffffu, tm1, 1));
        tm1 = fmaxf(tm1, __shfl_xor_sync(0xffffffffu, tm1, 2));
        float nm0 = fmaxf(m0, tm0), nm1 = fmaxf(m1, tm1);
        float a0 = fast_exp(m0 - nm0), a1 = fast_exp(m1 - nm1);
        m0 = nm0; m1 = nm1;
        float ps0 = 0.f, ps1 = 0.f;
        #pragma unroll
        for (int n = 0; n < 8; n++) {
            S[n][0] = fast_exp(S[n][0] - nm0); ps0 += S[n][0];
            S[n][1] = fast_exp(S[n][1] - nm0); ps0 += S[n][1];
            S[n][2] = fast_exp(S[n][2] - nm1); ps1 += S[n][2];
            S[n][3] = fast_exp(S[n][3] - nm1); ps1 += S[n][3];
        }
        ps0 += __shfl_xor_sync(0xffffffffu, ps0, 1);
        ps0 += __shfl_xor_sync(0xffffffffu, ps0, 2);
        ps1 += __shfl_xor_sync(0xffffffffu, ps1, 1);
        ps1 += __shfl_xor_sync(0xffffffffu, ps1, 2);
        l0 = l0 * a0 + ps0;
        l1 = l1 * a1 + ps1;
        #pragma unroll
        for (int n = 0; n < 8; n++) {
            o[n][0] *= a0; o[n][1] *= a0;
            o[n][2] *= a1; o[n][3] *= a1;
        }

        #pragma unroll
        for (int kk = 0; kk < 4; kk++) {
            uint32_t ph[4], pl[4];
            pack_split(S[2*kk][0],   S[2*kk][1],   ph[0], pl[0]);
            pack_split(S[2*kk][2],   S[2*kk][3],   ph[1], pl[1]);
            pack_split(S[2*kk+1][0], S[2*kk+1][1], ph[2], pl[2]);
            pack_split(S[2*kk+1][2], S[2*kk+1][3], ph[3], pl[3]);

            const int kb = kk * 16 + qc;
            uint32_t vf[8][2];
            #pragma unroll
            for (int n = 0; n < 8; n++) {
                int nr = n * 8 + (lane >> 2);
                vf[n][0] = *(const uint32_t*)(sVh + nr * FSKC + kb);
                vf[n][1] = *(const uint32_t*)(sVh + nr * FSKC + kb + 8);
            }
            #pragma unroll
            for (int n = 0; n < 8; n++) {
                mma_bf16(o[n], ph, vf[n]);
                mma_bf16(o[n], pl, vf[n]);
            }
            #pragma unroll
            for (int n = 0; n < 8; n++) {
                int nr = n * 8 + (lane >> 2);
                vf[n][0] = *(const uint32_t*)(sVl + nr * FSKC + kb);
                vf[n][1] = *(const uint32_t*)(sVl + nr * FSKC + kb + 8);
            }
            #pragma unroll
            for (int n = 0; n < 8; n++)
                mma_bf16(o[n], ph, vf[n]);
        }
    }

    const float inv0 = 1.0f / (l0 * 32.0f);
    const float inv1 = 1.0f / (l1 * 32.0f);
    const int bb = bh >> 4, hh = bh & 15;
    size_t base0 = ((size_t)(bb * SEQ + qr)) * DEMB + hh * DHEAD;
    size_t base1 = base0 + (size_t)8 * DEMB;
    #pragma unroll
    for (int n = 0; n < 8; n++) {
        int col = n * 8 + qc;
        uint32_t h0, l0w, h1, l1w;
        pack_split(o[n][0] * inv0, o[n][1] * inv0, h0, l0w);
        pack_split(o[n][2] * inv1, o[n][3] * inv1, h1, l1w);
        *(uint32_t*)(g_Ohi + base0 + col) = h0;
        *(uint32_t*)(g_Olo + base0 + col) = l0w;
        *(uint32_t*)(g_Ohi + base1 + col) = h1;
        *(uint32_t*)(g_Olo + base1 + col) = l1w;
    }
}

// ---------------------------------------------------------------------------
extern "C" void kernel_launch(void* const* d_in, const int* in_sizes, int n_in,
                              void* d_out, int out_size)
{
    const float* x      = (const float*)d_in[0];
    const float* w_qkv  = (const float*)d_in[1];
    const float* b_qkv  = (const float*)d_in[2];
    const float* w_proj = (const float*)d_in[3];
    const float* b_proj = (const float*)d_in[4];
    float* out = (float*)d_out;

    static int attr_set = 0;
    if (!attr_set) {
        cudaFuncSetAttribute(gemm_bf16_kernel<0>, cudaFuncAttributeMaxDynamicSharedMemorySize, GDYN);
        cudaFuncSetAttribute(gemm_bf16_kernel<1>, cudaFuncAttributeMaxDynamicSharedMemorySize, GDYN);
        cudaFuncSetAttribute(flash_tc_kernel,     cudaFuncAttributeMaxDynamicSharedMemorySize, FDYN);
        attr_set = 1;
    }

    cvt_x_kernel<<<8192, 256>>>((const float4*)x);
    cvt_wT_kernel<0><<<dim3(96, 32), dim3(32, 8)>>>(w_qkv);
    cvt_wT_kernel<1><<<dim3(32, 32), dim3(32, 8)>>>(w_proj);

    gemm_bf16_kernel<0><<<dim3(3072/128, MROWS/128), 256, GDYN>>>(b_qkv, nullptr);

    flash_tc_kernel<<<dim3(BATCH*NHEAD, SEQ/128), 256, FDYN>>>();

    gemm_bf16_kernel<1><<<dim3(1024/128, MROWS/128), 256, GDYN>>>(b_proj, out);
}

// round 12
// speedup vs baseline: 1.1153x; 1.0773x over previous
#include <cuda_runtime.h>
#include <cuda_bf16.h>
#include <stdint.h>
#include <math.h>

#define BATCH 8
#define SEQ   1024
#define DEMB  1024
#define NHEAD 16
#define DHEAD 64
#define MROWS (BATCH*SEQ)   // 8192

// ------------------------- scratch (device globals) -------------------------
__device__ __align__(16) __nv_bfloat16 g_Qhi[(size_t)BATCH*NHEAD*SEQ*DHEAD];
__device__ __align__(16) __nv_bfloat16 g_Qlo[(size_t)BATCH*NHEAD*SEQ*DHEAD];
__device__ __align__(16) __nv_bfloat16 g_Khi[(size_t)BATCH*NHEAD*SEQ*DHEAD];
__device__ __align__(16) __nv_bfloat16 g_Klo[(size_t)BATCH*NHEAD*SEQ*DHEAD];
__device__ __align__(16) __nv_bfloat16 g_Vthi[(size_t)BATCH*NHEAD*DHEAD*SEQ];  // [B,H,64,N]
__device__ __align__(16) __nv_bfloat16 g_Vtlo[(size_t)BATCH*NHEAD*DHEAD*SEQ];

__device__ __align__(16) __nv_bfloat16 g_Xhi[(size_t)MROWS*DEMB];
__device__ __align__(16) __nv_bfloat16 g_Xlo[(size_t)MROWS*DEMB];
__device__ __align__(16) __nv_bfloat16 g_WqThi[(size_t)3072*1024];
__device__ __align__(16) __nv_bfloat16 g_WqTlo[(size_t)3072*1024];
__device__ __align__(16) __nv_bfloat16 g_WpThi[(size_t)1024*1024];
__device__ __align__(16) __nv_bfloat16 g_WpTlo[(size_t)1024*1024];
__device__ __align__(16) __nv_bfloat16 g_Ohi[(size_t)MROWS*DEMB];
__device__ __align__(16) __nv_bfloat16 g_Olo[(size_t)MROWS*DEMB];

// ------------------------- helpers -------------------------
__device__ __forceinline__ uint32_t smem_u32(const void* p) {
    uint32_t a;
    asm("{ .reg .u64 t; cvta.to.shared.u64 t, %1; cvt.u32.u64 %0, t; }" : "=r"(a) : "l"(p));
    return a;
}
__device__ __forceinline__ void mma_bf16(float* d, const uint32_t* a, const uint32_t* b) {
    asm volatile("mma.sync.aligned.m16n8k16.row.col.f32.bf16.bf16.f32 "
                 "{%0,%1,%2,%3}, {%4,%5,%6,%7}, {%8,%9}, {%0,%1,%2,%3};"
                 : "+f"(d[0]), "+f"(d[1]), "+f"(d[2]), "+f"(d[3])
                 : "r"(a[0]), "r"(a[1]), "r"(a[2]), "r"(a[3]), "r"(b[0]), "r"(b[1]));
}
__device__ __forceinline__ void ldm_x4(uint32_t addr, uint32_t& r0, uint32_t& r1,
                                       uint32_t& r2, uint32_t& r3) {
    asm volatile("ldmatrix.sync.aligned.m8n8.x4.shared.b16 {%0,%1,%2,%3}, [%4];"
                 : "=r"(r0), "=r"(r1), "=r"(r2), "=r"(r3) : "r"(addr));
}
__device__ __forceinline__ void split2(float v, __nv_bfloat16& h, __nv_bfloat16& l) {
    h = __float2bfloat16(v);
    l = __float2bfloat16(v - __bfloat162float(h));
}
__device__ __forceinline__ void pack_split(float x, float y, uint32_t& hi, uint32_t& lo) {
    __nv_bfloat16 xh, xl, yh, yl;
    split2(x, xh, xl); split2(y, yh, yl);
    __nv_bfloat162 h2(xh, yh), l2(xl, yl);
    hi = *(uint32_t*)&h2; lo = *(uint32_t*)&l2;
}
// FMA-pipe exp; valid for x <= 0; rel err ~2e-6.
__device__ __forceinline__ float fast_exp(float x) {
    float y = fmaxf(x * 1.44269504088896340736f, -120.0f);
    float t = y + 12582912.0f;
    float n = t - 12582912.0f;
    float f = y - n;
    float p =        1.3333558e-3f;
    p = fmaf(p, f,   9.6181291e-3f);
    p = fmaf(p, f,   5.5504109e-2f);
    p = fmaf(p, f,   2.4022651e-1f);
    p = fmaf(p, f,   6.9314718e-1f);
    p = fmaf(p, f,   1.0f);
    int e = (int)n;
    float s = __int_as_float((e + 127) << 23);
    return p * s;
}

// ------------------------- conversion kernels -------------------------
__global__ __launch_bounds__(256) void cvt_x_kernel(const float4* __restrict__ X)
{
    __nv_bfloat162* hi = (__nv_bfloat162*)g_Xhi;
    __nv_bfloat162* lo = (__nv_bfloat162*)g_Xlo;
    int i = blockIdx.x * 256 + threadIdx.x;
    float4 v = X[i];
    __nv_bfloat16 h0,l0,h1,l1,h2,l2,h3,l3;
    split2(v.x,h0,l0); split2(v.y,h1,l1); split2(v.z,h2,l2); split2(v.w,h3,l3);
    hi[2*i]   = __nv_bfloat162(h0,h1); hi[2*i+1] = __nv_bfloat162(h2,h3);
    lo[2*i]   = __nv_bfloat162(l0,l1); lo[2*i+1] = __nv_bfloat162(l2,l3);
}

template<int WSEL>
__global__ __launch_bounds__(256) void cvt_wT_kernel(const float* __restrict__ W)
{
    const int ncols = (WSEL == 0) ? 3072 : 1024;
    __nv_bfloat16* hiT = (WSEL == 0) ? g_WqThi : g_WpThi;
    __nv_bfloat16* loT = (WSEL == 0) ? g_WqTlo : g_WpTlo;

    __shared__ float t[32][33];
    const int n0 = blockIdx.x * 32, k0 = blockIdx.y * 32;
    const int tx = threadIdx.x, ty = threadIdx.y;
    #pragma unroll
    for (int r = ty; r < 32; r += 8)
        t[r][tx] = W[(size_t)(k0 + r) * ncols + n0 + tx];
    __syncthreads();
    #pragma unroll
    for (int rr = ty; rr < 32; rr += 8) {
        float v = t[tx][rr];
        __nv_bfloat16 h, l; split2(v, h, l);
        size_t o = (size_t)(n0 + rr) * 1024 + k0 + tx;
        hiT[o] = h; loT[o] = l;
    }
}

// ------------------------- mma.sync split-bf16 GEMM -------------------------
// 128-thread CTAs, tile 128(M) x 64(N), 4 warps (4m x 1n, warp tile 32x64).
// 3 CTAs/SM (occupancy-driven overlap); double-buffer smem + reg prefetch +
// ldmatrix fragments; one barrier per K=64 chunk.
#define KC    64
#define SKC   72
#define AE    (128*SKC)           // A elems per buffer
#define BE    (64*SKC)            // B elems per buffer
#define STG   (AE+BE)             // elems per buffer
#define NCH   48                  // 3 passes x 16 chunks
#define GDYN  (2*STG*2)           // bytes = 55296

template<int MODE>   // 0: qkv (scatter hi/lo Q,K,Vt), 1: proj (store fp32)
__global__ __launch_bounds__(128, 3) void gemm_bf16_kernel(
    const float* __restrict__ bias, float* __restrict__ out)
{
    const __nv_bfloat16* __restrict__ Ahi = (MODE == 0) ? g_Xhi   : g_Ohi;
    const __nv_bfloat16* __restrict__ Alo = (MODE == 0) ? g_Xlo   : g_Olo;
    const __nv_bfloat16* __restrict__ Bhi = (MODE == 0) ? g_WqThi : g_WpThi;
    const __nv_bfloat16* __restrict__ Blo = (MODE == 0) ? g_WqTlo : g_WpTlo;

    extern __shared__ __align__(16) __nv_bfloat16 smem_dyn[];
    const uint32_t sb = smem_u32(smem_dyn);

    const int tid  = threadIdx.x;
    const int wid  = tid >> 5, lane = tid & 31;
    const int wm   = wid;                    // 4 m-warps, single n-warp
    const int bn   = blockIdx.x * 64;
    const int bm   = blockIdx.y * 128;

    float acc[2][8][4];
    #pragma unroll
    for (int mt = 0; mt < 2; mt++)
        #pragma unroll
        for (int n = 0; n < 8; n++)
            #pragma unroll
            for (int c = 0; c < 4; c++) acc[mt][n][c] = 0.f;

    const int lm_a_row = (lane & 15);
    const int lm_a_ch  = (lane >> 4) << 3;
    const int lm_b_row = (lane & 7) + (((lane >> 3) & 1) << 3);
    const int lm_b_ch  = (lane >> 4) << 3;

    // prefetch: A 8 x uint4 (1024 uint4 over 128 thr), B 4 x uint4 (512 uint4)
    uint4 ra[8], rb[4];
    auto issue_loads = [&](int i) {
        const int p  = i >> 4;                  // 0: hi*hi, 1: hi*lo, 2: lo*hi
        const int k0 = (i & 15) * KC;
        const __nv_bfloat16* Ap = (p == 2) ? Alo : Ahi;
        const __nv_bfloat16* Bp = (p == 1) ? Blo : Bhi;
        #pragma unroll
        for (int q = 0; q < 8; q++) {
            int idx = q * 128 + tid;
            int row = idx >> 3;
            int col = (idx & 7) * 8;
            ra[q] = *(const uint4*)(Ap + (size_t)(bm + row) * 1024 + k0 + col);
        }
        #pragma unroll
        for (int q = 0; q < 4; q++) {
            int idx = q * 128 + tid;
            int row = idx >> 3;
            int col = (idx & 7) * 8;
            rb[q] = *(const uint4*)(Bp + (size_t)(bn + row) * 1024 + k0 + col);
        }
    };
    issue_loads(0);

    for (int i = 0; i < NCH; i++) {
        const int bsel = i & 1;
        __nv_bfloat16* sA = smem_dyn + bsel * STG;
        __nv_bfloat16* sB = sA + AE;
        const uint32_t aAddr = sb + (uint32_t)bsel * (STG * 2);
        const uint32_t bAddr = aAddr + AE * 2;

        #pragma unroll
        for (int q = 0; q < 8; q++) {
            int idx = q * 128 + tid;
            int row = idx >> 3;
            int col = (idx & 7) * 8;
            *(uint4*)(sA + row * SKC + col) = ra[q];
        }
        #pragma unroll
        for (int q = 0; q < 4; q++) {
            int idx = q * 128 + tid;
            int row = idx >> 3;
            int col = (idx & 7) * 8;
            *(uint4*)(sB + row * SKC + col) = rb[q];
        }
        if (i + 1 < NCH) issue_loads(i + 1);
        __syncthreads();

        #pragma unroll
        for (int ks = 0; ks < 4; ks++) {
            const int cb = ks * 16;
            uint32_t afr[2][4];
            #pragma unroll
            for (int mt = 0; mt < 2; mt++) {
                int row = wm * 32 + mt * 16 + lm_a_row;
                int col = cb + lm_a_ch;
                ldm_x4(aAddr + (uint32_t)(row * SKC + col) * 2,
                       afr[mt][0], afr[mt][1], afr[mt][2], afr[mt][3]);
            }
            uint32_t bfr[8][2];
            #pragma unroll
            for (int ng = 0; ng < 4; ng++) {
                int row = ng * 16 + lm_b_row;
                int col = cb + lm_b_ch;
                uint32_t r0, r1, r2, r3;
                ldm_x4(bAddr + (uint32_t)(row * SKC + col) * 2, r0, r1, r2, r3);
                bfr[2*ng][0]   = r0; bfr[2*ng][1]   = r2;
                bfr[2*ng+1][0] = r1; bfr[2*ng+1][1] = r3;
            }
            #pragma unroll
            for (int mt = 0; mt < 2; mt++)
                #pragma unroll
                for (int n = 0; n < 8; n++)
                    mma_bf16(acc[mt][n], afr[mt], bfr[n]);
        }
    }

    // ---- epilogue ----
    #pragma unroll
    for (int mt = 0; mt < 2; mt++) {
        #pragma unroll
        for (int half = 0; half < 2; half++) {
            int gr = bm + wm * 32 + mt * 16 + (lane >> 2) + half * 8;
            if (MODE == 0) {
                const int bb = gr >> 10, nn = gr & 1023;
                #pragma unroll
                for (int n = 0; n < 8; n++) {
                    #pragma unroll
                    for (int e = 0; e < 2; e++) {
                        int gc = bn + n * 8 + 2 * (lane & 3) + e;
                        float v = acc[mt][n][half * 2 + e] + bias[gc];
                        int h  = gc / 192;
                        int rr = gc - h * 192;
                        int dd = rr / 3;
                        int which = rr - dd * 3;
                        __nv_bfloat16 vh, vl; split2(v, vh, vl);
                        if (which == 2) {
                            size_t idx = ((size_t)(bb * NHEAD + h) * DHEAD + dd) * SEQ + nn;
                            g_Vthi[idx] = vh; g_Vtlo[idx] = vl;
                        } else {
                            size_t idx = ((size_t)(bb * NHEAD + h) * SEQ + nn) * DHEAD + dd;
                            if (which == 0) { g_Qhi[idx] = vh; g_Qlo[idx] = vl; }
                            else            { g_Khi[idx] = vh; g_Klo[idx] = vl; }
                        }
                    }
                }
            } else {
                #pragma unroll
                for (int n = 0; n < 8; n++) {
                    int gc = bn + n * 8 + 2 * (lane & 3);
                    float2 v = make_float2(acc[mt][n][half*2]   + bias[gc],
                                           acc[mt][n][half*2+1] + bias[gc + 1]);
                    *(float2*)(out + (size_t)gr * 1024 + gc) = v;
                }
            }
        }
    }
}

// ------------------------- tensor-core flash attention (unchanged) ----------
#define FSKC 72
#define FMAT (64*FSKC)
#define FBUF (4*FMAT)
#define FDYN (FBUF*2*2)

__global__ __launch_bounds__(256, 1) void flash_tc_kernel()
{
    extern __shared__ __align__(16) __nv_bfloat16 fsm[];
    const int tid  = threadIdx.x;
    const int wid  = tid >> 5, lane = tid & 31;
    const int bh   = blockIdx.x;
    const int qr   = blockIdx.y * 128 + wid * 16 + (lane >> 2);
    const int qc   = (lane & 3) * 2;

    uint32_t qh[4][4], ql[4][4];
    {
        const __nv_bfloat16* Qh = g_Qhi + ((size_t)bh * SEQ + qr) * DHEAD;
        const __nv_bfloat16* Ql = g_Qlo + ((size_t)bh * SEQ + qr) * DHEAD;
        #pragma unroll
        for (int kk = 0; kk < 4; kk++) {
            int c = kk * 16 + qc;
            qh[kk][0] = *(const uint32_t*)(Qh + c);
            qh[kk][1] = *(const uint32_t*)(Qh + 8 * DHEAD + c);
            qh[kk][2] = *(const uint32_t*)(Qh + c + 8);
            qh[kk][3] = *(const uint32_t*)(Qh + 8 * DHEAD + c + 8);
            ql[kk][0] = *(const uint32_t*)(Ql + c);
            ql[kk][1] = *(const uint32_t*)(Ql + 8 * DHEAD + c);
            ql[kk][2] = *(const uint32_t*)(Ql + c + 8);
            ql[kk][3] = *(const uint32_t*)(Ql + 8 * DHEAD + c + 8);
        }
    }

    float o[8][4];
    #pragma unroll
    for (int n = 0; n < 8; n++)
        #pragma unroll
        for (int c = 0; c < 4; c++) o[n][c] = 0.f;
    float m0 = 0.f, m1 = 0.f, l0 = 0.f, l1 = 0.f;

    uint4 pre[8];
    auto issue_load = [&](int t) {
        const int key0 = t * 64;
        #pragma unroll
        for (int i = 0; i < 2; i++) {
            int u = i * 256 + tid;
            int row = u >> 3, c8 = (u & 7) * 8;
            size_t koff = ((size_t)bh * SEQ + key0 + row) * DHEAD + c8;
            size_t voff = ((size_t)bh * DHEAD + row) * SEQ + key0 + c8;
            pre[i]     = *(const uint4*)(g_Khi  + koff);
            pre[2 + i] = *(const uint4*)(g_Klo  + koff);
            pre[4 + i] = *(const uint4*)(g_Vthi + voff);
            pre[6 + i] = *(const uint4*)(g_Vtlo + voff);
        }
    };
    issue_load(0);

    for (int t = 0; t < SEQ / 64; t++) {
        __nv_bfloat16* buf = fsm + (t & 1) * FBUF;
        __nv_bfloat16* sKh = buf;
        __nv_bfloat16* sKl = buf + FMAT;
        __nv_bfloat16* sVh = buf + 2 * FMAT;
        __nv_bfloat16* sVl = buf + 3 * FMAT;

        #pragma unroll
        for (int i = 0; i < 2; i++) {
            int u = i * 256 + tid;
            int row = u >> 3, c8 = (u & 7) * 8;
            *(uint4*)(sKh + row * FSKC + c8) = pre[i];
            *(uint4*)(sKl + row * FSKC + c8) = pre[2 + i];
            *(uint4*)(sVh + row * FSKC + c8) = pre[4 + i];
            *(uint4*)(sVl + row * FSKC + c8) = pre[6 + i];
        }
        if (t + 1 < SEQ / 64) issue_load(t + 1);
        __syncthreads();

        float S[8][4];
        #pragma unroll
        for (int n = 0; n < 8; n++)
            #pragma unroll
            for (int c = 0; c < 4; c++) S[n][c] = 0.f;

        #pragma unroll
        for (int kk = 0; kk < 4; kk++) {
            const int kb = kk * 16 + qc;
            uint32_t kf[8][2];
            #pragma unroll
            for (int n = 0; n < 8; n++) {
                int nr = n * 8 + (lane >> 2);
                kf[n][0] = *(const uint32_t*)(sKh + nr * FSKC + kb);
                kf[n][1] = *(const uint32_t*)(sKh + nr * FSKC + kb + 8);
            }
            #pragma unroll
            for (int n = 0; n < 8; n++) {
                mma_bf16(S[n], qh[kk], kf[n]);
                mma_bf16(S[n], ql[kk], kf[n]);
            }
            #pragma unroll
            for (int n = 0; n < 8; n++) {
                int nr = n * 8 + (lane >> 2);
                kf[n][0] = *(const uint32_t*)(sKl + nr * FSKC + kb);
                kf[n][1] = *(const uint32_t*)(sKl + nr * FSKC + kb + 8);
            }
            #pragma unroll
            for (int n = 0; n < 8; n++)
                mma_bf16(S[n], qh[kk], kf[n]);
        }

        float tm0 = S[0][0], tm1 = S[0][2];
        #pragma unroll
        for (int n = 0; n < 8; n++) {
            tm0 = fmaxf(tm0, fmaxf(S[n][0], S[n][1]));
            tm1 = fmaxf(tm1, fmaxf(S[n][2], S[n][3]));
        }
        tm0 = fmaxf(tm0, __shfl_xor_sync(0xffffffffu, tm0, 1));
        tm0 = fmaxf(tm0, __shfl_xor_sync(0xffffffffu, tm0, 2));
        tm1 = fmaxf(tm1, __shfl_xor_sync(0xffffffffu, tm1, 1));
        tm1 = fmaxf(tm1, __shfl_xor_sync(0xffffffffu, tm1, 2));
        float nm0 = fmaxf(m0, tm0), nm1 = fmaxf(m1, tm1);
        float a0 = fast_exp(m0 - nm0), a1 = fast_exp(m1 - nm1);
        m0 = nm0; m1 = nm1;
        float ps0 = 0.f, ps1 = 0.f;
        #pragma unroll
        for (int n = 0; n < 8; n++) {
            S[n][0] = fast_exp(S[n][0] - nm0); ps0 += S[n][0];
            S[n][1] = fast_exp(S[n][1] - nm0); ps0 += S[n][1];
            S[n][2] = fast_exp(S[n][2] - nm1); ps1 += S[n][2];
            S[n][3] = fast_exp(S[n][3] - nm1); ps1 += S[n][3];
        }
        ps0 += __shfl_xor_sync(0xffffffffu, ps0, 1);
        ps0 += __shfl_xor_sync(0xffffffffu, ps0, 2);
        ps1 += __shfl_xor_sync(0xffffffffu, ps1, 1);
        ps1 += __shfl_xor_sync(0xffffffffu, ps1, 2);
        l0 = l0 * a0 + ps0;
        l1 = l1 * a1 + ps1;
        #pragma unroll
        for (int n = 0; n < 8; n++) {
            o[n][0] *= a0; o[n][1] *= a0;
            o[n][2] *= a1; o[n][3] *= a1;
        }

        #pragma unroll
        for (int kk = 0; kk < 4; kk++) {
            uint32_t ph[4], pl[4];
            pack_split(S[2*kk][0],   S[2*kk][1],   ph[0], pl[0]);
            pack_split(S[2*kk][2],   S[2*kk][3],   ph[1], pl[1]);
            pack_split(S[2*kk+1][0], S[2*kk+1][1], ph[2], pl[2]);
            pack_split(S[2*kk+1][2], S[2*kk+1][3], ph[3], pl[3]);

            const int kb = kk * 16 + qc;
            uint32_t vf[8][2];
            #pragma unroll
            for (int n = 0; n < 8; n++) {
                int nr = n * 8 + (lane >> 2);
                vf[n][0] = *(const uint32_t*)(sVh + nr * FSKC + kb);
                vf[n][1] = *(const uint32_t*)(sVh + nr * FSKC + kb + 8);
            }
            #pragma unroll
            for (int n = 0; n < 8; n++) {
                mma_bf16(o[n], ph, vf[n]);
                mma_bf16(o[n], pl, vf[n]);
            }
            #pragma unroll
            for (int n = 0; n < 8; n++) {
                int nr = n * 8 + (lane >> 2);
                vf[n][0] = *(const uint32_t*)(sVl + nr * FSKC + kb);
                vf[n][1] = *(const uint32_t*)(sVl + nr * FSKC + kb + 8);
            }
            #pragma unroll
            for (int n = 0; n < 8; n++)
                mma_bf16(o[n], ph, vf[n]);
        }
    }

    const float inv0 = 1.0f / (l0 * 32.0f);
    const float inv1 = 1.0f / (l1 * 32.0f);
    const int bb = bh >> 4, hh = bh & 15;
    size_t base0 = ((size_t)(bb * SEQ + qr)) * DEMB + hh * DHEAD;
    size_t base1 = base0 + (size_t)8 * DEMB;
    #pragma unroll
    for (int n = 0; n < 8; n++) {
        int col = n * 8 + qc;
        uint32_t h0, l0w, h1, l1w;
        pack_split(o[n][0] * inv0, o[n][1] * inv0, h0, l0w);
        pack_split(o[n][2] * inv1, o[n][3] * inv1, h1, l1w);
        *(uint32_t*)(g_Ohi + base0 + col) = h0;
        *(uint32_t*)(g_Olo + base0 + col) = l0w;
        *(uint32_t*)(g_Ohi + base1 + col) = h1;
        *(uint32_t*)(g_Olo + base1 + col) = l1w;
    }
}

// ---------------------------------------------------------------------------
extern "C" void kernel_launch(void* const* d_in, const int* in_sizes, int n_in,
                              void* d_out, int out_size)
{
    const float* x      = (const float*)d_in[0];
    const float* w_qkv  = (const float*)d_in[1];
    const float* b_qkv  = (const float*)d_in[2];
    const float* w_proj = (const float*)d_in[3];
    const float* b_proj = (const float*)d_in[4];
    float* out = (float*)d_out;

    static int attr_set = 0;
    if (!attr_set) {
        cudaFuncSetAttribute(gemm_bf16_kernel<0>, cudaFuncAttributeMaxDynamicSharedMemorySize, GDYN);
        cudaFuncSetAttribute(gemm_bf16_kernel<1>, cudaFuncAttributeMaxDynamicSharedMemorySize, GDYN);
        cudaFuncSetAttribute(flash_tc_kernel,     cudaFuncAttributeMaxDynamicSharedMemorySize, FDYN);
        attr_set = 1;
    }

    cvt_x_kernel<<<8192, 256>>>((const float4*)x);
    cvt_wT_kernel<0><<<dim3(96, 32), dim3(32, 8)>>>(w_qkv);
    cvt_wT_kernel<1><<<dim3(32, 32), dim3(32, 8)>>>(w_proj);

    // qkv: tiles 64(N)-wide -> grid (3072/64, 8192/128)
    gemm_bf16_kernel<0><<<dim3(3072/64, MROWS/128), 128, GDYN>>>(b_qkv, nullptr);

    flash_tc_kernel<<<dim3(BATCH*NHEAD, SEQ/128), 256, FDYN>>>();

    // proj: grid (1024/64, 8192/128)
    gemm_bf16_kernel<1><<<dim3(1024/64, MROWS/128), 128, GDYN>>>(b_proj, out);
}

// round 13
// speedup vs baseline: 1.1270x; 1.0105x over previous
#include <cuda_runtime.h>
#include <cuda_bf16.h>
#include <stdint.h>
#include <math.h>

#define BATCH 8
#define SEQ   1024
#define DEMB  1024
#define NHEAD 16
#define DHEAD 64
#define MROWS (BATCH*SEQ)   // 8192

// ------------------------- scratch (device globals) -------------------------
__device__ __align__(16) __nv_bfloat16 g_Qhi[(size_t)BATCH*NHEAD*SEQ*DHEAD];
__device__ __align__(16) __nv_bfloat16 g_Qlo[(size_t)BATCH*NHEAD*SEQ*DHEAD];
__device__ __align__(16) __nv_bfloat16 g_Khi[(size_t)BATCH*NHEAD*SEQ*DHEAD];
__device__ __align__(16) __nv_bfloat16 g_Klo[(size_t)BATCH*NHEAD*SEQ*DHEAD];
__device__ __align__(16) __nv_bfloat16 g_Vthi[(size_t)BATCH*NHEAD*DHEAD*SEQ];  // [B,H,64,N]
__device__ __align__(16) __nv_bfloat16 g_Vtlo[(size_t)BATCH*NHEAD*DHEAD*SEQ];

__device__ __align__(16) __nv_bfloat16 g_Xhi[(size_t)MROWS*DEMB];
__device__ __align__(16) __nv_bfloat16 g_Xlo[(size_t)MROWS*DEMB];
__device__ __align__(16) __nv_bfloat16 g_WqThi[(size_t)3072*1024];
__device__ __align__(16) __nv_bfloat16 g_WqTlo[(size_t)3072*1024];
__device__ __align__(16) __nv_bfloat16 g_WpThi[(size_t)1024*1024];
__device__ __align__(16) __nv_bfloat16 g_WpTlo[(size_t)1024*1024];
__device__ __align__(16) __nv_bfloat16 g_Ohi[(size_t)MROWS*DEMB];
__device__ __align__(16) __nv_bfloat16 g_Olo[(size_t)MROWS*DEMB];

// ------------------------- helpers -------------------------
__device__ __forceinline__ uint32_t smem_u32(const void* p) {
    uint32_t a;
    asm("{ .reg .u64 t; cvta.to.shared.u64 t, %1; cvt.u32.u64 %0, t; }" : "=r"(a) : "l"(p));
    return a;
}
__device__ __forceinline__ void mma_bf16(float* d, const uint32_t* a, const uint32_t* b) {
    asm volatile("mma.sync.aligned.m16n8k16.row.col.f32.bf16.bf16.f32 "
                 "{%0,%1,%2,%3}, {%4,%5,%6,%7}, {%8,%9}, {%0,%1,%2,%3};"
                 : "+f"(d[0]), "+f"(d[1]), "+f"(d[2]), "+f"(d[3])
                 : "r"(a[0]), "r"(a[1]), "r"(a[2]), "r"(a[3]), "r"(b[0]), "r"(b[1]));
}
__device__ __forceinline__ void ldm_x4(uint32_t addr, uint32_t& r0, uint32_t& r1,
                                       uint32_t& r2, uint32_t& r3) {
    asm volatile("ldmatrix.sync.aligned.m8n8.x4.shared.b16 {%0,%1,%2,%3}, [%4];"
                 : "=r"(r0), "=r"(r1), "=r"(r2), "=r"(r3) : "r"(addr));
}
__device__ __forceinline__ void split2(float v, __nv_bfloat16& h, __nv_bfloat16& l) {
    h = __float2bfloat16(v);
    l = __float2bfloat16(v - __bfloat162float(h));
}
__device__ __forceinline__ void pack_split(float x, float y, uint32_t& hi, uint32_t& lo) {
    __nv_bfloat16 xh, xl, yh, yl;
    split2(x, xh, xl); split2(y, yh, yl);
    __nv_bfloat162 h2(xh, yh), l2(xl, yl);
    hi = *(uint32_t*)&h2; lo = *(uint32_t*)&l2;
}
// FMA-pipe exp; valid for x <= 0; rel err ~2e-6.
__device__ __forceinline__ float fast_exp(float x) {
    float y = fmaxf(x * 1.44269504088896340736f, -120.0f);
    float t = y + 12582912.0f;
    float n = t - 12582912.0f;
    float f = y - n;
    float p =        1.3333558e-3f;
    p = fmaf(p, f,   9.6181291e-3f);
    p = fmaf(p, f,   5.5504109e-2f);
    p = fmaf(p, f,   2.4022651e-1f);
    p = fmaf(p, f,   6.9314718e-1f);
    p = fmaf(p, f,   1.0f);
    int e = (int)n;
    float s = __int_as_float((e + 127) << 23);
    return p * s;
}

// ------------------------- conversion kernels -------------------------
__global__ __launch_bounds__(256) void cvt_x_kernel(const float4* __restrict__ X)
{
    __nv_bfloat162* hi = (__nv_bfloat162*)g_Xhi;
    __nv_bfloat162* lo = (__nv_bfloat162*)g_Xlo;
    int i = blockIdx.x * 256 + threadIdx.x;
    float4 v = X[i];
    __nv_bfloat16 h0,l0,h1,l1,h2,l2,h3,l3;
    split2(v.x,h0,l0); split2(v.y,h1,l1); split2(v.z,h2,l2); split2(v.w,h3,l3);
    hi[2*i]   = __nv_bfloat162(h0,h1); hi[2*i+1] = __nv_bfloat162(h2,h3);
    lo[2*i]   = __nv_bfloat162(l0,l1); lo[2*i+1] = __nv_bfloat162(l2,l3);
}

template<int WSEL>
__global__ __launch_bounds__(256) void cvt_wT_kernel(const float* __restrict__ W)
{
    const int ncols = (WSEL == 0) ? 3072 : 1024;
    __nv_bfloat16* hiT = (WSEL == 0) ? g_WqThi : g_WpThi;
    __nv_bfloat16* loT = (WSEL == 0) ? g_WqTlo : g_WpTlo;

    __shared__ float t[32][33];
    const int n0 = blockIdx.x * 32, k0 = blockIdx.y * 32;
    const int tx = threadIdx.x, ty = threadIdx.y;
    #pragma unroll
    for (int r = ty; r < 32; r += 8)
        t[r][tx] = W[(size_t)(k0 + r) * ncols + n0 + tx];
    __syncthreads();
    #pragma unroll
    for (int rr = ty; rr < 32; rr += 8) {
        float v = t[tx][rr];
        __nv_bfloat16 h, l; split2(v, h, l);
        size_t o = (size_t)(n0 + rr) * 1024 + k0 + tx;
        hiT[o] = h; loT[o] = l;
    }
}

// ------------------------- mma.sync split-bf16 GEMM (fused hi/lo chunks) ----
// Each K=32 chunk loads Ahi,Alo,Bhi,Blo ONCE into smem, then accumulates all
// three split terms (Ahi*Bhi + Alo*Bhi + Ahi*Blo) from that single copy:
// 33% less LDG/STS/LDSM traffic per MMA than the 3-pass scheme.
// 128-thread CTAs, tile 128(M) x 64(N), 3 CTAs/SM, double-buffered smem.
#define KC    32
#define SKC   40                  // padded row stride (elems); 80B rows
#define AE    (128*SKC)           // one A matrix per buffer (elems)
#define BE    (64*SKC)            // one B matrix per buffer
#define STG   (2*AE+2*BE)         // elems per buffer (Ahi,Alo,Bhi,Blo) = 15360
#define NCH   32                  // K=1024 / 32
#define GDYN  (2*STG*2)           // bytes = 61440

template<int MODE>   // 0: qkv (scatter hi/lo Q,K,Vt), 1: proj (store fp32)
__global__ __launch_bounds__(128, 3) void gemm_bf16_kernel(
    const float* __restrict__ bias, float* __restrict__ out)
{
    const __nv_bfloat16* __restrict__ Ahi = (MODE == 0) ? g_Xhi   : g_Ohi;
    const __nv_bfloat16* __restrict__ Alo = (MODE == 0) ? g_Xlo   : g_Olo;
    const __nv_bfloat16* __restrict__ Bhi = (MODE == 0) ? g_WqThi : g_WpThi;
    const __nv_bfloat16* __restrict__ Blo = (MODE == 0) ? g_WqTlo : g_WpTlo;

    extern __shared__ __align__(16) __nv_bfloat16 smem_dyn[];
    const uint32_t sb = smem_u32(smem_dyn);

    const int tid  = threadIdx.x;
    const int wid  = tid >> 5, lane = tid & 31;
    const int wm   = wid;                    // 4 m-warps, single n-warp
    const int bn   = blockIdx.x * 64;
    const int bm   = blockIdx.y * 128;

    float acc[2][8][4];
    #pragma unroll
    for (int mt = 0; mt < 2; mt++)
        #pragma unroll
        for (int n = 0; n < 8; n++)
            #pragma unroll
            for (int c = 0; c < 4; c++) acc[mt][n][c] = 0.f;

    const int lm_a_row = (lane & 15);
    const int lm_a_ch  = (lane >> 4) << 3;
    const int lm_b_row = (lane & 7) + (((lane >> 3) & 1) << 3);
    const int lm_b_ch  = (lane >> 4) << 3;

    // prefetch regs: A hi/lo 4 uint4 each, B hi/lo 2 each (12 total)
    uint4 rah[4], ral[4], rbh[2], rbl[2];
    auto issue_loads = [&](int i) {
        const int k0 = i * KC;
        #pragma unroll
        for (int q = 0; q < 4; q++) {
            int idx = q * 128 + tid;            // 0..511
            int row = idx >> 2;                 // 0..127 (4 uint4 per row)
            int col = (idx & 3) * 8;            // 0,8,16,24
            size_t off = (size_t)(bm + row) * 1024 + k0 + col;
            rah[q] = *(const uint4*)(Ahi + off);
            ral[q] = *(const uint4*)(Alo + off);
        }
        #pragma unroll
        for (int q = 0; q < 2; q++) {
            int idx = q * 128 + tid;            // 0..255
            int row = idx >> 2;                 // 0..63
            int col = (idx & 3) * 8;
            size_t off = (size_t)(bn + row) * 1024 + k0 + col;
            rbh[q] = *(const uint4*)(Bhi + off);
            rbl[q] = *(const uint4*)(Blo + off);
        }
    };
    issue_loads(0);

    for (int i = 0; i < NCH; i++) {
        const int bsel = i & 1;
        __nv_bfloat16* sAh = smem_dyn + bsel * STG;
        __nv_bfloat16* sAl = sAh + AE;
        __nv_bfloat16* sBh = sAl + AE;
        __nv_bfloat16* sBl = sBh + BE;
        const uint32_t aHad = sb + (uint32_t)bsel * (STG * 2);
        const uint32_t aLad = aHad + AE * 2;
        const uint32_t bHad = aLad + AE * 2;
        const uint32_t bLad = bHad + BE * 2;

        #pragma unroll
        for (int q = 0; q < 4; q++) {
            int idx = q * 128 + tid;
            int row = idx >> 2;
            int col = (idx & 3) * 8;
            *(uint4*)(sAh + row * SKC + col) = rah[q];
            *(uint4*)(sAl + row * SKC + col) = ral[q];
        }
        #pragma unroll
        for (int q = 0; q < 2; q++) {
            int idx = q * 128 + tid;
            int row = idx >> 2;
            int col = (idx & 3) * 8;
            *(uint4*)(sBh + row * SKC + col) = rbh[q];
            *(uint4*)(sBl + row * SKC + col) = rbl[q];
        }
        if (i + 1 < NCH) issue_loads(i + 1);
        __syncthreads();

        #pragma unroll
        for (int ks = 0; ks < 2; ks++) {
            const int cb = ks * 16;
            // Ahi + Bhi fragments
            uint32_t ah[2][4];
            #pragma unroll
            for (int mt = 0; mt < 2; mt++) {
                int row = wm * 32 + mt * 16 + lm_a_row;
                ldm_x4(aHad + (uint32_t)(row * SKC + cb + lm_a_ch) * 2,
                       ah[mt][0], ah[mt][1], ah[mt][2], ah[mt][3]);
            }
            uint32_t bh[8][2];
            #pragma unroll
            for (int ng = 0; ng < 4; ng++) {
                int row = ng * 16 + lm_b_row;
                uint32_t r0, r1, r2, r3;
                ldm_x4(bHad + (uint32_t)(row * SKC + cb + lm_b_ch) * 2, r0, r1, r2, r3);
                bh[2*ng][0]   = r0; bh[2*ng][1]   = r2;
                bh[2*ng+1][0] = r1; bh[2*ng+1][1] = r3;
            }
            #pragma unroll
            for (int mt = 0; mt < 2; mt++)
                #pragma unroll
                for (int n = 0; n < 8; n++)
                    mma_bf16(acc[mt][n], ah[mt], bh[n]);

            // Alo * Bhi (Bhi still live)
            uint32_t al[2][4];
            #pragma unroll
            for (int mt = 0; mt < 2; mt++) {
                int row = wm * 32 + mt * 16 + lm_a_row;
                ldm_x4(aLad + (uint32_t)(row * SKC + cb + lm_a_ch) * 2,
                       al[mt][0], al[mt][1], al[mt][2], al[mt][3]);
            }
            #pragma unroll
            for (int mt = 0; mt < 2; mt++)
                #pragma unroll
                for (int n = 0; n < 8; n++)
                    mma_bf16(acc[mt][n], al[mt], bh[n]);

            // Ahi * Blo (Bhi regs dead; Blo reuses)
            uint32_t bl[8][2];
            #pragma unroll
            for (int ng = 0; ng < 4; ng++) {
                int row = ng * 16 + lm_b_row;
                uint32_t r0, r1, r2, r3;
                ldm_x4(bLad + (uint32_t)(row * SKC + cb + lm_b_ch) * 2, r0, r1, r2, r3);
                bl[2*ng][0]   = r0; bl[2*ng][1]   = r2;
                bl[2*ng+1][0] = r1; bl[2*ng+1][1] = r3;
            }
            #pragma unroll
            for (int mt = 0; mt < 2; mt++)
                #pragma unroll
                for (int n = 0; n < 8; n++)
                    mma_bf16(acc[mt][n], ah[mt], bl[n]);
        }
    }

    // ---- epilogue ----
    #pragma unroll
    for (int mt = 0; mt < 2; mt++) {
        #pragma unroll
        for (int half = 0; half < 2; half++) {
            int gr = bm + wm * 32 + mt * 16 + (lane >> 2) + half * 8;
            if (MODE == 0) {
                const int bb = gr >> 10, nn = gr & 1023;
                #pragma unroll
                for (int n = 0; n < 8; n++) {
                    #pragma unroll
                    for (int e = 0; e < 2; e++) {
                        int gc = bn + n * 8 + 2 * (lane & 3) + e;
                        float v = acc[mt][n][half * 2 + e] + bias[gc];
                        int h  = gc / 192;
                        int rr = gc - h * 192;
                        int dd = rr / 3;
                        int which = rr - dd * 3;
                        __nv_bfloat16 vh, vl; split2(v, vh, vl);
                        if (which == 2) {
                            size_t idx = ((size_t)(bb * NHEAD + h) * DHEAD + dd) * SEQ + nn;
                            g_Vthi[idx] = vh; g_Vtlo[idx] = vl;
                        } else {
                            size_t idx = ((size_t)(bb * NHEAD + h) * SEQ + nn) * DHEAD + dd;
                            if (which == 0) { g_Qhi[idx] = vh; g_Qlo[idx] = vl; }
                            else            { g_Khi[idx] = vh; g_Klo[idx] = vl; }
                        }
                    }
                }
            } else {
                #pragma unroll
                for (int n = 0; n < 8; n++) {
                    int gc = bn + n * 8 + 2 * (lane & 3);
                    float2 v = make_float2(acc[mt][n][half*2]   + bias[gc],
                                           acc[mt][n][half*2+1] + bias[gc + 1]);
                    *(float2*)(out + (size_t)gr * 1024 + gc) = v;
                }
            }
        }
    }
}

// ------------------------- tensor-core flash attention (unchanged) ----------
#define FSKC 72
#define FMAT (64*FSKC)
#define FBUF (4*FMAT)
#define FDYN (FBUF*2*2)

__global__ __launch_bounds__(256, 1) void flash_tc_kernel()
{
    extern __shared__ __align__(16) __nv_bfloat16 fsm[];
    const int tid  = threadIdx.x;
    const int wid  = tid >> 5, lane = tid & 31;
    const int bh   = blockIdx.x;
    const int qr   = blockIdx.y * 128 + wid * 16 + (lane >> 2);
    const int qc   = (lane & 3) * 2;

    uint32_t qh[4][4], ql[4][4];
    {
        const __nv_bfloat16* Qh = g_Qhi + ((size_t)bh * SEQ + qr) * DHEAD;
        const __nv_bfloat16* Ql = g_Qlo + ((size_t)bh * SEQ + qr) * DHEAD;
        #pragma unroll
        for (int kk = 0; kk < 4; kk++) {
            int c = kk * 16 + qc;
            qh[kk][0] = *(const uint32_t*)(Qh + c);
            qh[kk][1] = *(const uint32_t*)(Qh + 8 * DHEAD + c);
            qh[kk][2] = *(const uint32_t*)(Qh + c + 8);
            qh[kk][3] = *(const uint32_t*)(Qh + 8 * DHEAD + c + 8);
            ql[kk][0] = *(const uint32_t*)(Ql + c);
            ql[kk][1] = *(const uint32_t*)(Ql + 8 * DHEAD + c);
            ql[kk][2] = *(const uint32_t*)(Ql + c + 8);
            ql[kk][3] = *(const uint32_t*)(Ql + 8 * DHEAD + c + 8);
        }
    }

    float o[8][4];
    #pragma unroll
    for (int n = 0; n < 8; n++)
        #pragma unroll
        for (int c = 0; c < 4; c++) o[n][c] = 0.f;
    float m0 = 0.f, m1 = 0.f, l0 = 0.f, l1 = 0.f;

    uint4 pre[8];
    auto issue_load = [&](int t) {
        const int key0 = t * 64;
        #pragma unroll
        for (int i = 0; i < 2; i++) {
            int u = i * 256 + tid;
            int row = u >> 3, c8 = (u & 7) * 8;
            size_t koff = ((size_t)bh * SEQ + key0 + row) * DHEAD + c8;
            size_t voff = ((size_t)bh * DHEAD + row) * SEQ + key0 + c8;
            pre[i]     = *(const uint4*)(g_Khi  + koff);
            pre[2 + i] = *(const uint4*)(g_Klo  + koff);
            pre[4 + i] = *(const uint4*)(g_Vthi + voff);
            pre[6 + i] = *(const uint4*)(g_Vtlo + voff);
        }
    };
    issue_load(0);

    for (int t = 0; t < SEQ / 64; t++) {
        __nv_bfloat16* buf = fsm + (t & 1) * FBUF;
        __nv_bfloat16* sKh = buf;
        __nv_bfloat16* sKl = buf + FMAT;
        __nv_bfloat16* sVh = buf + 2 * FMAT;
        __nv_bfloat16* sVl = buf + 3 * FMAT;

        #pragma unroll
        for (int i = 0; i < 2; i++) {
            int u = i * 256 + tid;
            int row = u >> 3, c8 = (u & 7) * 8;
            *(uint4*)(sKh + row * FSKC + c8) = pre[i];
            *(uint4*)(sKl + row * FSKC + c8) = pre[2 + i];
            *(uint4*)(sVh + row * FSKC + c8) = pre[4 + i];
            *(uint4*)(sVl + row * FSKC + c8) = pre[6 + i];
        }
        if (t + 1 < SEQ / 64) issue_load(t + 1);
        __syncthreads();

        float S[8][4];
        #pragma unroll
        for (int n = 0; n < 8; n++)
            #pragma unroll
            for (int c = 0; c < 4; c++) S[n][c] = 0.f;

        #pragma unroll
        for (int kk = 0; kk < 4; kk++) {
            const int kb = kk * 16 + qc;
            uint32_t kf[8][2];
            #pragma unroll
            for (int n = 0; n < 8; n++) {
                int nr = n * 8 + (lane >> 2);
                kf[n][0] = *(const uint32_t*)(sKh + nr * FSKC + kb);
                kf[n][1] = *(const uint32_t*)(sKh + nr * FSKC + kb + 8);
            }
            #pragma unroll
            for (int n = 0; n < 8; n++) {
                mma_bf16(S[n], qh[kk], kf[n]);
                mma_bf16(S[n], ql[kk], kf[n]);
            }
            #pragma unroll
            for (int n = 0; n < 8; n++) {
                int nr = n * 8 + (lane >> 2);
                kf[n][0] = *(const uint32_t*)(sKl + nr * FSKC + kb);
                kf[n][1] = *(const uint32_t*)(sKl + nr * FSKC + kb + 8);
            }
            #pragma unroll
            for (int n = 0; n < 8; n++)
                mma_bf16(S[n], qh[kk], kf[n]);
        }

        float tm0 = S[0][0], tm1 = S[0][2];
        #pragma unroll
        for (int n = 0; n < 8; n++) {
            tm0 = fmaxf(tm0, fmaxf(S[n][0], S[n][1]));
            tm1 = fmaxf(tm1, fmaxf(S[n][2], S[n][3]));
        }
        tm0 = fmaxf(tm0, __shfl_xor_sync(0xffffffffu, tm0, 1));
        tm0 = fmaxf(tm0, __shfl_xor_sync(0xffffffffu, tm0, 2));
        tm1 = fmaxf(tm1, __shfl_xor_sync(0xffffffffu, tm1, 1));
        tm1 = fmaxf(tm1, __shfl_xor_sync(0xffffffffu, tm1, 2));
        float nm0 = fmaxf(m0, tm0), nm1 = fmaxf(m1, tm1);
        float a0 = fast_exp(m0 - nm0), a1 = fast_exp(m1 - nm1);
        m0 = nm0; m1 = nm1;
        float ps0 = 0.f, ps1 = 0.f;
        #pragma unroll
        for (int n = 0; n < 8; n++) {
            S[n][0] = fast_exp(S[n][0] - nm0); ps0 += S[n][0];
            S[n][1] = fast_exp(S[n][1] - nm0); ps0 += S[n][1];
            S[n][2] = fast_exp(S[n][2] - nm1); ps1 += S[n][2];
            S[n][3] = fast_exp(S[n][3] - nm1); ps1 += S[n][3];
        }
        ps0 += __shfl_xor_sync(0xffffffffu, ps0, 1);
        ps0 += __shfl_xor_sync(0xffffffffu, ps0, 2);
        ps1 += __shfl_xor_sync(0xffffffffu, ps1, 1);
        ps1 += __shfl_xor_sync(0xffffffffu, ps1, 2);
        l0 = l0 * a0 + ps0;
        l1 = l1 * a1 + ps1;
        #pragma unroll
        for (int n = 0; n < 8; n++) {
            o[n][0] *= a0; o[n][1] *= a0;
            o[n][2] *= a1; o[n][3] *= a1;
        }

        #pragma unroll
        for (int kk = 0; kk < 4; kk++) {
            uint32_t ph[4], pl[4];
            pack_split(S[2*kk][0],   S[2*kk][1],   ph[0], pl[0]);
            pack_split(S[2*kk][2],   S[2*kk][3],   ph[1], pl[1]);
            pack_split(S[2*kk+1][0], S[2*kk+1][1], ph[2], pl[2]);
            pack_split(S[2*kk+1][2], S[2*kk+1][3], ph[3], pl[3]);

            const int kb = kk * 16 + qc;
            uint32_t vf[8][2];
            #pragma unroll
            for (int n = 0; n < 8; n++) {
                int nr = n * 8 + (lane >> 2);
                vf[n][0] = *(const uint32_t*)(sVh + nr * FSKC + kb);
                vf[n][1] = *(const uint32_t*)(sVh + nr * FSKC + kb + 8);
            }
            #pragma unroll
            for (int n = 0; n < 8; n++) {
                mma_bf16(o[n], ph, vf[n]);
                mma_bf16(o[n], pl, vf[n]);
            }
            #pragma unroll
            for (int n = 0; n < 8; n++) {
                int nr = n * 8 + (lane >> 2);
                vf[n][0] = *(const uint32_t*)(sVl + nr * FSKC + kb);
                vf[n][1] = *(const uint32_t*)(sVl + nr * FSKC + kb + 8);
            }
            #pragma unroll
            for (int n = 0; n < 8; n++)
                mma_bf16(o[n], ph, vf[n]);
        }
    }

    const float inv0 = 1.0f / (l0 * 32.0f);
    const float inv1 = 1.0f / (l1 * 32.0f);
    const int bb = bh >> 4, hh = bh & 15;
    size_t base0 = ((size_t)(bb * SEQ + qr)) * DEMB + hh * DHEAD;
    size_t base1 = base0 + (size_t)8 * DEMB;
    #pragma unroll
    for (int n = 0; n < 8; n++) {
        int col = n * 8 + qc;
        uint32_t h0, l0w, h1, l1w;
        pack_split(o[n][0] * inv0, o[n][1] * inv0, h0, l0w);
        pack_split(o[n][2] * inv1, o[n][3] * inv1, h1, l1w);
        *(uint32_t*)(g_Ohi + base0 + col) = h0;
        *(uint32_t*)(g_Olo + base0 + col) = l0w;
        *(uint32_t*)(g_Ohi + base1 + col) = h1;
        *(uint32_t*)(g_Olo + base1 + col) = l1w;
    }
}

// ---------------------------------------------------------------------------
extern "C" void kernel_launch(void* const* d_in, const int* in_sizes, int n_in,
                              void* d_out, int out_size)
{
    const float* x      = (const float*)d_in[0];
    const float* w_qkv  = (const float*)d_in[1];
    const float* b_qkv  = (const float*)d_in[2];
    const float* w_proj = (const float*)d_in[3];
    const float* b_proj = (const float*)d_in[4];
    float* out = (float*)d_out;

    static int attr_set = 0;
    if (!attr_set) {
        cudaFuncSetAttribute(gemm_bf16_kernel<0>, cudaFuncAttributeMaxDynamicSharedMemorySize, GDYN);
        cudaFuncSetAttribute(gemm_bf16_kernel<1>, cudaFuncAttributeMaxDynamicSharedMemorySize, GDYN);
        cudaFuncSetAttribute(flash_tc_kernel,     cudaFuncAttributeMaxDynamicSharedMemorySize, FDYN);
        attr_set = 1;
    }

    cvt_x_kernel<<<8192, 256>>>((const float4*)x);
    cvt_wT_kernel<0><<<dim3(96, 32), dim3(32, 8)>>>(w_qkv);
    cvt_wT_kernel<1><<<dim3(32, 32), dim3(32, 8)>>>(w_proj);

    gemm_bf16_kernel<0><<<dim3(3072/64, MROWS/128), 128, GDYN>>>(b_qkv, nullptr);

    flash_tc_kernel<<<dim3(BATCH*NHEAD, SEQ/128), 256, FDYN>>>();

    gemm_bf16_kernel<1><<<dim3(1024/64, MROWS/128), 128, GDYN>>>(b_proj, out);
}